// round 16
// baseline (speedup 1.0000x reference)
#include <cuda_runtime.h>
#include <cuda_bf16.h>
#include <cstdint>

#define B_      32
#define CIN_    128
#define H_      56
#define W_      56
#define COUT_   256
#define HW_     (H_ * W_)
#define KDIM_   (CIN_ * 9)
#define NX_     (B_ * CIN_ * HW_)
#define NW_     (COUT_ * CIN_ * 9)
#define XP_ROWS 58

__device__ unsigned g_amax_x_bits;    // zero-initialized at load; replay-stable
__device__ unsigned g_amax_w_bits;
// activations, quantized s8, pre-transposed: [b][hp 0..57][wp 0..63][ci 0..127]
__device__ __align__(16) char g_qxp[B_ * XP_ROWS * 64 * 128];
// weights, quantized s8: [co][tap*128 + ci]
__device__ __align__(16) char g_qw[COUT_ * KDIM_];

__device__ __forceinline__ float xla_div(float a, float b) {
    float r;
    asm("div.full.f32 %0, %1, %2;" : "=f"(r) : "f"(a), "f"(b));
    return r;
}
__device__ __forceinline__ float quant1(float v, float s) {
    float r = rintf(xla_div(v, s));
    return fminf(fmaxf(r, -8.0f), 7.0f);
}

// ---- fused absmax over x and w (one launch) ----
#define XBLK 4096
#define WBLK 64
__global__ void k_absmax2(const float* __restrict__ x, const float* __restrict__ w) {
    int tid = threadIdx.x, lane = tid & 31, warp = tid >> 5;
    const bool isw = blockIdx.x >= XBLK;
    const float4* p4 = reinterpret_cast<const float4*>(isw ? w : x);
    const int n4 = isw ? (NW_ / 4) : (NX_ / 4);
    const int bid = isw ? (blockIdx.x - XBLK) : blockIdx.x;
    const int nb  = isw ? WBLK : XBLK;
    float m = 0.0f;
    for (long long i = (long long)bid * blockDim.x + tid; i < n4;
         i += (long long)nb * blockDim.x) {
        float4 v = p4[i];
        m = fmaxf(m, fmaxf(fmaxf(fabsf(v.x), fabsf(v.y)), fmaxf(fabsf(v.z), fabsf(v.w))));
    }
    #pragma unroll
    for (int off = 16; off; off >>= 1) m = fmaxf(m, __shfl_xor_sync(~0u, m, off));
    __shared__ float sm[8];
    if (lane == 0) sm[warp] = m;
    __syncthreads();
    if (warp == 0) {
        m = (lane < 8) ? sm[lane] : 0.0f;
        #pragma unroll
        for (int off = 4; off; off >>= 1) m = fmaxf(m, __shfl_xor_sync(~0u, m, off));
        if (lane == 0) atomicMax(isw ? &g_amax_w_bits : &g_amax_x_bits, __float_as_uint(m));
    }
}

// quantize + transpose x: one block per (hp, b). Output row (b,hp): [wp][ci] s8.
__global__ void k_quant_xt(const float* __restrict__ x) {
    __shared__ char sq[64 * 132];         // [wp][ci], rows padded to 132B
    const int tid = threadIdx.x;
    const int hp = blockIdx.x, b = blockIdx.y;
    char* dst = g_qxp + ((long long)(b * XP_ROWS + hp) * 64) * 128;

    if (hp == 0 || hp == 57) {            // border: zeros
        #pragma unroll
        for (int j = 0; j < 8; j++)
            *reinterpret_cast<unsigned*>(dst + tid * 32 + j * 4) = 0u;
        return;
    }
    for (int i = tid * 4; i < 64 * 132; i += 256 * 4)
        *reinterpret_cast<unsigned*>(sq + i) = 0u;
    __syncthreads();

    const float s = xla_div(__uint_as_float(g_amax_x_bits), 7.5f);
    // 32 ci-quads x 14 w-groups = 448 units; each: 4ci x 4w block -> 4 packed words
    #pragma unroll
    for (int i = 0; i < 2; i++) {
        int v = i * 256 + tid;
        if (v < 448) {
            int ci4 = v / 14, wg = v - ci4 * 14;
            const float* base = x + ((long long)(b * CIN_ + ci4 * 4) * H_ + (hp - 1)) * W_ + wg * 4;
            float4 d0 = *reinterpret_cast<const float4*>(base);
            float4 d1 = *reinterpret_cast<const float4*>(base + HW_);
            float4 d2 = *reinterpret_cast<const float4*>(base + 2 * HW_);
            float4 d3 = *reinterpret_cast<const float4*>(base + 3 * HW_);
            unsigned wq[4];
            #pragma unroll
            for (int k = 0; k < 4; k++) {
                float e0 = k == 0 ? d0.x : k == 1 ? d0.y : k == 2 ? d0.z : d0.w;
                float e1 = k == 0 ? d1.x : k == 1 ? d1.y : k == 2 ? d1.z : d1.w;
                float e2 = k == 0 ? d2.x : k == 1 ? d2.y : k == 2 ? d2.z : d2.w;
                float e3 = k == 0 ? d3.x : k == 1 ? d3.y : k == 2 ? d3.z : d3.w;
                wq[k] = ((unsigned)((int)quant1(e0, s) & 0xFF)) |
                        ((unsigned)((int)quant1(e1, s) & 0xFF) << 8) |
                        ((unsigned)((int)quant1(e2, s) & 0xFF) << 16) |
                        ((unsigned)((int)quant1(e3, s) & 0xFF) << 24);
            }
            int wp0 = wg * 4 + 1;
            #pragma unroll
            for (int k = 0; k < 4; k++)
                *reinterpret_cast<unsigned*>(sq + (wp0 + k) * 132 + ci4 * 4) = wq[k];
        }
    }
    __syncthreads();
    {
        int wp = tid >> 2, ci0 = (tid & 3) * 32;
        #pragma unroll
        for (int j = 0; j < 8; j++)
            *reinterpret_cast<unsigned*>(dst + wp * 128 + ci0 + j * 4) =
                *reinterpret_cast<const unsigned*>(sq + wp * 132 + ci0 + j * 4);
    }
}

__global__ void k_quant_w(const float* __restrict__ w) {
    int idx = blockIdx.x * blockDim.x + threadIdx.x;
    float s = xla_div(__uint_as_float(g_amax_w_bits), 7.5f);
    int co = idx / KDIM_;
    int rem = idx - co * KDIM_;
    int ci = rem / 9;
    int t  = rem - ci * 9;
    g_qw[co * KDIM_ + t * CIN_ + ci] = (char)(int)quant1(w[idx], s);
}

// ---- conv: s8 IMMA, 512 thr, warp=M16x56, M=128 x 2 rows, K=128/tap ----
#define AS_LD 144                   // bytes per A row (128 data + 16 pad)
#define ABUF  (128 * AS_LD)         // 18432 per stage
#define TS_W  144                   // bytes per wp row (128 data + 16 pad)
#define TS_R  (66 * TS_W)           // 9504 per input row
#define OFF_T (3 * ABUF)            // 55296
#define SMEM_CONV (OFF_T + 4 * TS_R)  // 93312

__global__ void __launch_bounds__(512, 2)
k_conv(const float* __restrict__ bias, float* __restrict__ out) {
    extern __shared__ __align__(16) char smem[];
    char* A = smem;
    char* T = smem + OFF_T;

    const int tid = threadIdx.x, warp = tid >> 5, lane = tid & 31;
    const int wm8 = warp & 7, wn = warp >> 3;     // wm8: M16 tile, wn: output row
    const int co0 = blockIdx.x * 128;
    const int h0  = blockIdx.y * 2;               // output rows h0, h0+1
    const int b   = blockIdx.z;

    int acc[7][4];
    #pragma unroll
    for (int nt = 0; nt < 7; nt++)
        #pragma unroll
        for (int i = 0; i < 4; i++) acc[nt][i] = 0;

    const uint32_t Abase = (uint32_t)__cvta_generic_to_shared(A);
    const uint32_t Tbase = (uint32_t)__cvta_generic_to_shared(T);

    const int quad = lane >> 3, lr = lane & 7;
    const uint32_t aoff = (wm8 * 16 + (quad & 1) * 8 + lr) * AS_LD + (quad >> 1) * 16;
    uint32_t boff[4];
    #pragma unroll
    for (int pr = 0; pr < 4; pr++)
        boff[pr] = ((pr * 2 + (quad >> 1)) * 8 + lr) * TS_W + (quad & 1) * 16;

    // ---- fill T once: 4 input rows x 64 wp x 128 ci bytes ----
    #pragma unroll
    for (int i = 0; i < 4; i++) {
        int v = i * 512 + tid;                    // 0..2047
        int ch = v & 7, wp = (v >> 3) & 63, r = v >> 9;
        const uint4 d = *reinterpret_cast<const uint4*>(
            g_qxp + ((long long)((b * XP_ROWS + h0 + r) * 64 + wp)) * 128 + ch * 16);
        *reinterpret_cast<uint4*>(T + r * TS_R + wp * TS_W + ch * 16) = d;
    }
    // ---- prefetch A taps 0,1 (full K=128): 1024 x 16B per stage ----
    #pragma unroll
    for (int p = 0; p < 2; p++) {
        #pragma unroll
        for (int i = 0; i < 2; i++) {
            int v = i * 512 + tid;                // 0..1023
            int row = v >> 3, ch = v & 7;
            const void* src = g_qw + (co0 + row) * KDIM_ + p * CIN_ + ch * 16;
            uint32_t dst = Abase + p * ABUF + row * AS_LD + ch * 16;
            asm volatile("cp.async.cg.shared.global [%0], [%1], 16;" :: "r"(dst), "l"(src));
        }
        asm volatile("cp.async.commit_group;");
    }

    for (int s = 0; s < 9; s++) {
        if (s < 8) asm volatile("cp.async.wait_group 1;");
        else       asm volatile("cp.async.wait_group 0;");
        __syncthreads();

        const int rrow = s / 3, dxp = s % 3;
        const uint32_t abufb = Abase + (s % 3) * ABUF;
        const uint32_t bbase = Tbase + (rrow + wn) * TS_R + dxp * TS_W;

        if (s + 2 < 9) {                          // prefetch tap s+2
            int p = s + 2;
            #pragma unroll
            for (int i = 0; i < 2; i++) {
                int v = i * 512 + tid;
                int row = v >> 3, ch = v & 7;
                const void* src = g_qw + (co0 + row) * KDIM_ + p * CIN_ + ch * 16;
                uint32_t dst = Abase + (p % 3) * ABUF + row * AS_LD + ch * 16;
                asm volatile("cp.async.cg.shared.global [%0], [%1], 16;" :: "r"(dst), "l"(src));
            }
            asm volatile("cp.async.commit_group;");
        }

        #pragma unroll
        for (int c = 0; c < 4; c++) {             // K32 chunks of the tap
            unsigned af[4], bf[8][2];
            asm volatile("ldmatrix.sync.aligned.m8n8.x4.shared.b16 {%0,%1,%2,%3}, [%4];"
                : "=r"(af[0]), "=r"(af[1]), "=r"(af[2]), "=r"(af[3])
                : "r"(abufb + aoff + c * 32));
            #pragma unroll
            for (int pr = 0; pr < 4; pr++)
                asm volatile("ldmatrix.sync.aligned.m8n8.x4.shared.b16 {%0,%1,%2,%3}, [%4];"
                    : "=r"(bf[pr * 2][0]), "=r"(bf[pr * 2][1]),
                      "=r"(bf[pr * 2 + 1][0]), "=r"(bf[pr * 2 + 1][1])
                    : "r"(bbase + boff[pr] + c * 32));
            #pragma unroll
            for (int nt = 0; nt < 7; nt++)         // nt=7 would be dead work
                asm volatile(
                    "mma.sync.aligned.m16n8k32.row.col.s32.s8.s8.s32 "
                    "{%0,%1,%2,%3}, {%4,%5,%6,%7}, {%8,%9}, {%0,%1,%2,%3};\n"
                    : "+r"(acc[nt][0]), "+r"(acc[nt][1]),
                      "+r"(acc[nt][2]), "+r"(acc[nt][3])
                    : "r"(af[0]), "r"(af[1]), "r"(af[2]), "r"(af[3]),
                      "r"(bf[nt][0]), "r"(bf[nt][1]));
        }
    }
    asm volatile("cp.async.wait_group 0;");

    // ---- epilogue ----
    const int g = lane >> 2, tg = lane & 3;
    const float sx = xla_div(__uint_as_float(g_amax_x_bits), 7.5f);
    const float sw = xla_div(__uint_as_float(g_amax_w_bits), 7.5f);
    const float scale = sx * sw;
    const int h = h0 + wn;
    {
        int r0 = co0 + wm8 * 16 + g;
        int r1 = r0 + 8;
        float bias0 = bias[r0];
        float bias1 = bias[r1];
        #pragma unroll
        for (int nt = 0; nt < 7; nt++) {
            int n = nt * 8 + tg * 2;              // 0..54, always < 56
            float2 v0, v1;
            v0.x = fmaf((float)acc[nt][0], scale, bias0);
            v0.y = fmaf((float)acc[nt][1], scale, bias0);
            v1.x = fmaf((float)acc[nt][2], scale, bias1);
            v1.y = fmaf((float)acc[nt][3], scale, bias1);
            long long o0 = ((long long)b * COUT_ + r0) * HW_ + h * 56 + n;
            long long o1 = ((long long)b * COUT_ + r1) * HW_ + h * 56 + n;
            *reinterpret_cast<float2*>(&out[o0]) = v0;
            *reinterpret_cast<float2*>(&out[o1]) = v1;
        }
    }
}

extern "C" void kernel_launch(void* const* d_in, const int* in_sizes, int n_in,
                              void* d_out, int out_size) {
    const float* x    = (const float*)d_in[0];
    const float* w    = (const float*)d_in[1];
    const float* bias = (const float*)d_in[2];
    float* out        = (float*)d_out;

    cudaFuncSetAttribute(k_conv, cudaFuncAttributeMaxDynamicSharedMemorySize, SMEM_CONV);
    k_absmax2<<<XBLK + WBLK, 256>>>(x, w);
    {
        dim3 gq(XP_ROWS, B_);
        k_quant_xt<<<gq, 256>>>(x);
    }
    k_quant_w<<<NW_ / 256, 256>>>(w);
    dim3 grid(COUT_ / 128, H_ / 2, B_);
    k_conv<<<grid, 512, SMEM_CONV>>>(bias, out);
}

// round 17
// speedup vs baseline: 1.0864x; 1.0864x over previous
#include <cuda_runtime.h>
#include <cuda_bf16.h>
#include <cstdint>

#define B_      32
#define CIN_    128
#define H_      56
#define W_      56
#define COUT_   256
#define HW_     (H_ * W_)
#define KDIM_   (CIN_ * 9)
#define NX_     (B_ * CIN_ * HW_)
#define NW_     (COUT_ * CIN_ * 9)
#define XP_ROWS 58

__device__ unsigned g_amax_x_bits;    // zero-initialized at load; replay-stable
__device__ unsigned g_amax_w_bits;
// activations, quantized s8, pre-transposed: [b][hp 0..57][wp 0..63][ci 0..127]
__device__ __align__(16) char g_qxp[B_ * XP_ROWS * 64 * 128];
// weights, quantized s8: [co][tap*128 + ci]
__device__ __align__(16) char g_qw[COUT_ * KDIM_];

__device__ __forceinline__ float xla_div(float a, float b) {
    float r;
    asm("div.full.f32 %0, %1, %2;" : "=f"(r) : "f"(a), "f"(b));
    return r;
}
__device__ __forceinline__ float quant1(float v, float s) {
    float r = rintf(xla_div(v, s));
    return fminf(fmaxf(r, -8.0f), 7.0f);
}

// ---- fused absmax over x and w (one launch) ----
#define XBLK 4096
#define WBLK 64
__global__ void k_absmax2(const float* __restrict__ x, const float* __restrict__ w) {
    int tid = threadIdx.x, lane = tid & 31, warp = tid >> 5;
    const bool isw = blockIdx.x >= XBLK;
    const float4* p4 = reinterpret_cast<const float4*>(isw ? w : x);
    const int n4 = isw ? (NW_ / 4) : (NX_ / 4);
    const int bid = isw ? (blockIdx.x - XBLK) : blockIdx.x;
    const int nb  = isw ? WBLK : XBLK;
    float m = 0.0f;
    for (long long i = (long long)bid * blockDim.x + tid; i < n4;
         i += (long long)nb * blockDim.x) {
        float4 v = p4[i];
        m = fmaxf(m, fmaxf(fmaxf(fabsf(v.x), fabsf(v.y)), fmaxf(fabsf(v.z), fabsf(v.w))));
    }
    #pragma unroll
    for (int off = 16; off; off >>= 1) m = fmaxf(m, __shfl_xor_sync(~0u, m, off));
    __shared__ float sm[8];
    if (lane == 0) sm[warp] = m;
    __syncthreads();
    if (warp == 0) {
        m = (lane < 8) ? sm[lane] : 0.0f;
        #pragma unroll
        for (int off = 4; off; off >>= 1) m = fmaxf(m, __shfl_xor_sync(~0u, m, off));
        if (lane == 0) atomicMax(isw ? &g_amax_w_bits : &g_amax_x_bits, __float_as_uint(m));
    }
}

// quantize + transpose x: one block per (hp, b). Output row (b,hp): [wp][ci] s8.
__global__ void k_quant_xt(const float* __restrict__ x) {
    __shared__ char sq[64 * 132];         // [wp][ci], rows padded to 132B
    const int tid = threadIdx.x;
    const int hp = blockIdx.x, b = blockIdx.y;
    char* dst = g_qxp + ((long long)(b * XP_ROWS + hp) * 64) * 128;

    if (hp == 0 || hp == 57) {            // border: zeros
        #pragma unroll
        for (int j = 0; j < 8; j++)
            *reinterpret_cast<unsigned*>(dst + tid * 32 + j * 4) = 0u;
        return;
    }
    for (int i = tid * 4; i < 64 * 132; i += 256 * 4)
        *reinterpret_cast<unsigned*>(sq + i) = 0u;
    __syncthreads();

    const float s = xla_div(__uint_as_float(g_amax_x_bits), 7.5f);
    // 32 ci-quads x 14 w-groups = 448 units; each: 4ci x 4w block -> 4 packed words
    #pragma unroll
    for (int i = 0; i < 2; i++) {
        int v = i * 256 + tid;
        if (v < 448) {
            int ci4 = v / 14, wg = v - ci4 * 14;
            const float* base = x + ((long long)(b * CIN_ + ci4 * 4) * H_ + (hp - 1)) * W_ + wg * 4;
            float4 d0 = *reinterpret_cast<const float4*>(base);
            float4 d1 = *reinterpret_cast<const float4*>(base + HW_);
            float4 d2 = *reinterpret_cast<const float4*>(base + 2 * HW_);
            float4 d3 = *reinterpret_cast<const float4*>(base + 3 * HW_);
            unsigned wq[4];
            #pragma unroll
            for (int k = 0; k < 4; k++) {
                float e0 = k == 0 ? d0.x : k == 1 ? d0.y : k == 2 ? d0.z : d0.w;
                float e1 = k == 0 ? d1.x : k == 1 ? d1.y : k == 2 ? d1.z : d1.w;
                float e2 = k == 0 ? d2.x : k == 1 ? d2.y : k == 2 ? d2.z : d2.w;
                float e3 = k == 0 ? d3.x : k == 1 ? d3.y : k == 2 ? d3.z : d3.w;
                wq[k] = ((unsigned)((int)quant1(e0, s) & 0xFF)) |
                        ((unsigned)((int)quant1(e1, s) & 0xFF) << 8) |
                        ((unsigned)((int)quant1(e2, s) & 0xFF) << 16) |
                        ((unsigned)((int)quant1(e3, s) & 0xFF) << 24);
            }
            int wp0 = wg * 4 + 1;
            #pragma unroll
            for (int k = 0; k < 4; k++)
                *reinterpret_cast<unsigned*>(sq + (wp0 + k) * 132 + ci4 * 4) = wq[k];
        }
    }
    __syncthreads();
    {
        int wp = tid >> 2, ci0 = (tid & 3) * 32;
        #pragma unroll
        for (int j = 0; j < 8; j++)
            *reinterpret_cast<unsigned*>(dst + wp * 128 + ci0 + j * 4) =
                *reinterpret_cast<const unsigned*>(sq + wp * 132 + ci0 + j * 4);
    }
}

__global__ void k_quant_w(const float* __restrict__ w) {
    int idx = blockIdx.x * blockDim.x + threadIdx.x;
    float s = xla_div(__uint_as_float(g_amax_w_bits), 7.5f);
    int co = idx / KDIM_;
    int rem = idx - co * KDIM_;
    int ci = rem / 9;
    int t  = rem - ci * 9;
    g_qw[co * KDIM_ + t * CIN_ + ci] = (char)(int)quant1(w[idx], s);
}

// ---- conv: s8 IMMA, M=128 x 2 rows; ALL 9 taps resident; barrier-free loop ----
#define AS_LD 80                    // bytes per A row (64 ci data + 16 pad)
#define ATAP  (128 * AS_LD)         // 10240 per tap
#define OFF_T (9 * ATAP)            // 92160
#define TS_W  80                    // bytes per wp row (64 ci data + 16 pad)
#define TS_R  (66 * TS_W)           // 5280 per input row
#define SMEM_CONV (OFF_T + 4 * TS_R)  // 113280

__global__ void __launch_bounds__(256, 2)
k_conv(const float* __restrict__ bias, float* __restrict__ out) {
    extern __shared__ __align__(16) char smem[];
    char* T = smem + OFF_T;

    const int tid = threadIdx.x, warp = tid >> 5, lane = tid & 31;
    const int wm = warp & 3, wn = warp >> 2;      // wn = output row 0..1
    const int co0 = blockIdx.x * 128;
    const int h0  = blockIdx.y * 2;               // output rows h0, h0+1
    const int b   = blockIdx.z;

    int acc[2][7][4];
    #pragma unroll
    for (int mt = 0; mt < 2; mt++)
        #pragma unroll
        for (int nt = 0; nt < 7; nt++)
            #pragma unroll
            for (int i = 0; i < 4; i++) acc[mt][nt][i] = 0;

    const uint32_t Abase = (uint32_t)__cvta_generic_to_shared(smem);
    const uint32_t Tbase = (uint32_t)__cvta_generic_to_shared(T);

    const int quad = lane >> 3, lr = lane & 7;
    uint32_t aoff[2], boff[4];
    #pragma unroll
    for (int mt = 0; mt < 2; mt++)
        aoff[mt] = (wm * 32 + mt * 16 + (quad & 1) * 8 + lr) * AS_LD + (quad >> 1) * 16;
    #pragma unroll
    for (int pr = 0; pr < 4; pr++)
        boff[pr] = ((pr * 2 + (quad >> 1)) * 8 + lr) * TS_W + (quad & 1) * 16;

    // ---- fill helpers ----
    // A: 9 taps x 128 rows x 64B (4608 x 16B => 18 per thread)
    #define FILL_A(cih)                                                              \
        do {                                                                         \
            _Pragma("unroll")                                                        \
            for (int i_ = 0; i_ < 18; i_++) {                                        \
                int v_ = i_ * 256 + tid;                                             \
                int tap_ = v_ / 512, r2_ = v_ - tap_ * 512;                          \
                int row_ = r2_ >> 2, ch_ = r2_ & 3;                                  \
                const void* src_ = g_qw + (co0 + row_) * KDIM_ + tap_ * CIN_ +       \
                                   (cih) * 64 + ch_ * 16;                            \
                uint32_t dst_ = Abase + tap_ * ATAP + row_ * AS_LD + ch_ * 16;       \
                asm volatile("cp.async.cg.shared.global [%0], [%1], 16;"             \
                             :: "r"(dst_), "l"(src_));                               \
            }                                                                        \
            asm volatile("cp.async.commit_group;");                                  \
        } while (0)
    // T: 4 rows x 64 wp x 64B (1024 x 16B => 4 per thread)
    #define FILL_T(cih)                                                              \
        do {                                                                         \
            _Pragma("unroll")                                                        \
            for (int i_ = 0; i_ < 4; i_++) {                                         \
                int v_ = i_ * 256 + tid;                                             \
                int ch_ = v_ & 3, wp_ = (v_ >> 2) & 63, r_ = v_ >> 8;                \
                const uint4 d_ = *reinterpret_cast<const uint4*>(                    \
                    g_qxp + ((long long)((b * XP_ROWS + h0 + r_) * 64 + wp_)) * 128  \
                          + (cih) * 64 + ch_ * 16);                                  \
                *reinterpret_cast<uint4*>(T + r_ * TS_R + wp_ * TS_W + ch_ * 16) = d_; \
            }                                                                        \
        } while (0)

    FILL_A(0);
    FILL_T(0);
    asm volatile("cp.async.wait_group 0;");
    __syncthreads();

    #pragma unroll 1
    for (int cih = 0; cih < 2; cih++) {
        #pragma unroll
        for (int s = 0; s < 9; s++) {
            const int rrow = s / 3, dxp = s % 3;
            const uint32_t abufb = Abase + s * ATAP;
            const uint32_t bbase = Tbase + (rrow + wn) * TS_R + dxp * TS_W;
            #pragma unroll
            for (int c = 0; c < 2; c++) {         // K32 chunks of this ci-half
                unsigned af[2][4], bf[8][2];
                #pragma unroll
                for (int mt = 0; mt < 2; mt++)
                    asm volatile("ldmatrix.sync.aligned.m8n8.x4.shared.b16 {%0,%1,%2,%3}, [%4];"
                        : "=r"(af[mt][0]), "=r"(af[mt][1]), "=r"(af[mt][2]), "=r"(af[mt][3])
                        : "r"(abufb + aoff[mt] + c * 32));
                #pragma unroll
                for (int pr = 0; pr < 4; pr++)
                    asm volatile("ldmatrix.sync.aligned.m8n8.x4.shared.b16 {%0,%1,%2,%3}, [%4];"
                        : "=r"(bf[pr * 2][0]), "=r"(bf[pr * 2][1]),
                          "=r"(bf[pr * 2 + 1][0]), "=r"(bf[pr * 2 + 1][1])
                        : "r"(bbase + boff[pr] + c * 32));
                #pragma unroll
                for (int mt = 0; mt < 2; mt++)
                    #pragma unroll
                    for (int nt = 0; nt < 7; nt++)   // nt=7 would be dead work
                        asm volatile(
                            "mma.sync.aligned.m16n8k32.row.col.s32.s8.s8.s32 "
                            "{%0,%1,%2,%3}, {%4,%5,%6,%7}, {%8,%9}, {%0,%1,%2,%3};\n"
                            : "+r"(acc[mt][nt][0]), "+r"(acc[mt][nt][1]),
                              "+r"(acc[mt][nt][2]), "+r"(acc[mt][nt][3])
                            : "r"(af[mt][0]), "r"(af[mt][1]), "r"(af[mt][2]), "r"(af[mt][3]),
                              "r"(bf[nt][0]), "r"(bf[nt][1]));
            }
        }
        if (cih == 0) {                           // swap in second ci-half
            __syncthreads();                      // everyone done reading A/T
            FILL_A(1);
            FILL_T(1);
            asm volatile("cp.async.wait_group 0;");
            __syncthreads();
        }
    }

    // ---- epilogue ----
    const int g = lane >> 2, tg = lane & 3;
    const float sx = xla_div(__uint_as_float(g_amax_x_bits), 7.5f);
    const float sw = xla_div(__uint_as_float(g_amax_w_bits), 7.5f);
    const float scale = sx * sw;
    const int h = h0 + wn;
    #pragma unroll
    for (int mt = 0; mt < 2; mt++) {
        int r0 = co0 + wm * 32 + mt * 16 + g;
        int r1 = r0 + 8;
        float bias0 = bias[r0];
        float bias1 = bias[r1];
        #pragma unroll
        for (int nt = 0; nt < 7; nt++) {
            int n = nt * 8 + tg * 2;              // 0..54, always < 56
            float2 v0, v1;
            v0.x = fmaf((float)acc[mt][nt][0], scale, bias0);
            v0.y = fmaf((float)acc[mt][nt][1], scale, bias0);
            v1.x = fmaf((float)acc[mt][nt][2], scale, bias1);
            v1.y = fmaf((float)acc[mt][nt][3], scale, bias1);
            long long o0 = ((long long)b * COUT_ + r0) * HW_ + h * 56 + n;
            long long o1 = ((long long)b * COUT_ + r1) * HW_ + h * 56 + n;
            *reinterpret_cast<float2*>(&out[o0]) = v0;
            *reinterpret_cast<float2*>(&out[o1]) = v1;
        }
    }
}

extern "C" void kernel_launch(void* const* d_in, const int* in_sizes, int n_in,
                              void* d_out, int out_size) {
    const float* x    = (const float*)d_in[0];
    const float* w    = (const float*)d_in[1];
    const float* bias = (const float*)d_in[2];
    float* out        = (float*)d_out;

    cudaFuncSetAttribute(k_conv, cudaFuncAttributeMaxDynamicSharedMemorySize, SMEM_CONV);
    k_absmax2<<<XBLK + WBLK, 256>>>(x, w);
    {
        dim3 gq(XP_ROWS, B_);
        k_quant_xt<<<gq, 256>>>(x);
    }
    k_quant_w<<<NW_ / 256, 256>>>(w);
    dim3 grid(COUT_ / 128, H_ / 2, B_);
    k_conv<<<grid, 256, SMEM_CONV>>>(bias, out);
}